// round 4
// baseline (speedup 1.0000x reference)
#include <cuda_runtime.h>
#include <cuda_bf16.h>
#include <cstdint>

// ============================================================================
// SimplifiedTopologyExtractor — algebraic reduction:
//   out = ReLU(LayerNorm(emb[:, :, :256] @ W_enc + b_enc))
// (pooled == embeddings exactly; proj/cdist/topk is dead code.)
//
// fp32 GEMM via bf16 hi/lo split on the legacy tensor path (mma.sync m16n8k16;
// tcgen05 needs the sm_103a PTX target this harness does not emit):
//   a*b ≈ ah*bh + ah*bl + al*bh   (err ~2^-18 rel).
// Round 4: term-major MMA ordering — 8 independent MMAs between any two
// writes to the same accumulator (was 3 back-to-back dependent MMAs),
// to fill the tensor pipe at the regfile-forced 8-warp occupancy.
// ============================================================================

#define THREADS 256
#define MTILE 64
#define NN 512
#define KD 256
#define KCH 16
#define NCHUNK (KD / KCH)

// smem strides/offsets (bytes)
#define A_STRIDE 48            // 16 bf16 (32B) + 16B pad -> conflict-free LDSM
#define B_STRIDE 1040          // 512 bf16 (1024B) + 16B pad
#define OFF_AH 0
#define OFF_AL (64 * A_STRIDE)                  // 3072
#define OFF_BH (2 * 64 * A_STRIDE)              // 6144
#define OFF_BL (OFF_BH + KCH * B_STRIDE)        // 22784
#define STAGE  (OFF_BL + KCH * B_STRIDE)        // 39424
#define OFF_PS (2 * STAGE)                      // 78848
#define OFF_PQ (OFF_PS + 2048)
#define OFF_MZ (OFF_PQ + 2048)
#define SMEM_TOTAL (OFF_MZ + 512)               // 83456

__device__ __forceinline__ uint32_t smem_u32(const void* p) {
    uint32_t a;
    asm("{ .reg .u64 t; cvta.to.shared.u64 t, %1; cvt.u32.u64 %0, t; }"
        : "=r"(a) : "l"(p));
    return a;
}

__device__ __forceinline__ void ldsm4(uint32_t* r, uint32_t addr) {
    asm volatile("ldmatrix.sync.aligned.m8n8.x4.shared.b16 {%0,%1,%2,%3}, [%4];"
                 : "=r"(r[0]), "=r"(r[1]), "=r"(r[2]), "=r"(r[3]) : "r"(addr));
}
__device__ __forceinline__ void ldsm4t(uint32_t* r, uint32_t addr) {
    asm volatile("ldmatrix.sync.aligned.m8n8.x4.trans.shared.b16 {%0,%1,%2,%3}, [%4];"
                 : "=r"(r[0]), "=r"(r[1]), "=r"(r[2]), "=r"(r[3]) : "r"(addr));
}

__device__ __forceinline__ void mma16816(float* d, const uint32_t* a,
                                         uint32_t b0, uint32_t b1) {
    asm volatile(
        "mma.sync.aligned.m16n8k16.row.col.f32.bf16.bf16.f32 "
        "{%0,%1,%2,%3}, {%4,%5,%6,%7}, {%8,%9}, {%0,%1,%2,%3};"
        : "+f"(d[0]), "+f"(d[1]), "+f"(d[2]), "+f"(d[3])
        : "r"(a[0]), "r"(a[1]), "r"(a[2]), "r"(a[3]), "r"(b0), "r"(b1));
}

// split float4 -> hi/lo bf16x2 pairs (elements n,n+1 packed lo/hi 16 bits)
__device__ __forceinline__ void split_f4(float4 v, uint32_t& h01, uint32_t& h23,
                                         uint32_t& l01, uint32_t& l23) {
    float f[4] = {v.x, v.y, v.z, v.w};
    unsigned short hs[4], ls[4];
#pragma unroll
    for (int i = 0; i < 4; i++) {
        __nv_bfloat16 h = __float2bfloat16(f[i]);
        float rem = f[i] - __bfloat162float(h);
        __nv_bfloat16 l = __float2bfloat16(rem);
        hs[i] = __bfloat16_as_ushort(h);
        ls[i] = __bfloat16_as_ushort(l);
    }
    h01 = (uint32_t)hs[0] | ((uint32_t)hs[1] << 16);
    h23 = (uint32_t)hs[2] | ((uint32_t)hs[3] << 16);
    l01 = (uint32_t)ls[0] | ((uint32_t)ls[1] << 16);
    l23 = (uint32_t)ls[2] | ((uint32_t)ls[3] << 16);
}

__global__ void __launch_bounds__(THREADS)
gemm_ln_kernel(const float* __restrict__ emb,
               const float* __restrict__ W,
               const float* __restrict__ bias,
               const float* __restrict__ gamma,
               const float* __restrict__ beta,
               float* __restrict__ out)
{
    extern __shared__ __align__(1024) unsigned char smem[];
    const uint32_t sb = smem_u32(smem);
    const int tid = threadIdx.x;
    const int wid = tid >> 5;
    const int lane = tid & 31;
    const int m0 = blockIdx.x * MTILE;

    float acc[4][8][4];
#pragma unroll
    for (int mt = 0; mt < 4; mt++)
#pragma unroll
        for (int nt = 0; nt < 8; nt++)
#pragma unroll
            for (int e = 0; e < 4; e++) acc[mt][nt][e] = 0.0f;

    // gmem staging mappings
    const int ar = tid >> 2, ac = tid & 3;     // A: 64 rows x 4 quads of k
    const int br = tid >> 4, bc = tid & 15;    // B: 16 rows x 16 col4 base
    float4 aS;
    float4 bS[8];

    // prologue: chunk 0
    aS = *(const float4*)(emb + (size_t)(m0 + ar) * 512 + ac * 4);
#pragma unroll
    for (int i = 0; i < 8; i++)
        bS[i] = *(const float4*)(W + (size_t)br * 512 + (bc + i * 16) * 4);

    // ldmatrix lane addressing
    const uint32_t lrow = lane & 15, lchk = lane >> 4;
    const uint32_t aLane = lrow * A_STRIDE + lchk * 16;
    const uint32_t bLane = lrow * B_STRIDE + lchk * 16 + (uint32_t)wid * 128;

#pragma unroll 1
    for (int c = 0; c < NCHUNK; ++c) {
        const uint32_t st = (c & 1) ? (uint32_t)STAGE : 0u;

        // ---- STS chunk c (convert in-register) ----
        {
            uint32_t h01, h23, l01, l23;
            split_f4(aS, h01, h23, l01, l23);
            *(uint2*)(smem + st + OFF_AH + ar * A_STRIDE + ac * 8) = make_uint2(h01, h23);
            *(uint2*)(smem + st + OFF_AL + ar * A_STRIDE + ac * 8) = make_uint2(l01, l23);
#pragma unroll
            for (int i = 0; i < 8; i++) {
                split_f4(bS[i], h01, h23, l01, l23);
                *(uint2*)(smem + st + OFF_BH + br * B_STRIDE + (bc + i * 16) * 8) =
                    make_uint2(h01, h23);
                *(uint2*)(smem + st + OFF_BL + br * B_STRIDE + (bc + i * 16) * 8) =
                    make_uint2(l01, l23);
            }
        }
        __syncthreads();

        // ---- prefetch chunk c+1 into registers (overlaps with MMA) ----
        if (c + 1 < NCHUNK) {
            const int k0 = (c + 1) * KCH;
            aS = *(const float4*)(emb + (size_t)(m0 + ar) * 512 + k0 + ac * 4);
#pragma unroll
            for (int i = 0; i < 8; i++)
                bS[i] = *(const float4*)(W + (size_t)(k0 + br) * 512 + (bc + i * 16) * 4);
        }

        // ---- MMA sweep on chunk c (term-major: 8 independent MMAs/group) ----
        uint32_t Ah[4][4], Al[4][4];
#pragma unroll
        for (int mt = 0; mt < 4; mt++) {
            ldsm4(Ah[mt], sb + st + OFF_AH + (uint32_t)mt * 16 * A_STRIDE + aLane);
            ldsm4(Al[mt], sb + st + OFF_AL + (uint32_t)mt * 16 * A_STRIDE + aLane);
        }
#pragma unroll
        for (int j = 0; j < 4; j++) {
            uint32_t Bh[4], Bl[4];
            ldsm4t(Bh, sb + st + OFF_BH + (uint32_t)j * 32 + bLane);
            ldsm4t(Bl, sb + st + OFF_BL + (uint32_t)j * 32 + bLane);
            // group 1: Ah * Bh  (8 independent accumulators)
#pragma unroll
            for (int mt = 0; mt < 4; mt++)
#pragma unroll
                for (int nn = 0; nn < 2; nn++)
                    mma16816(acc[mt][j * 2 + nn], Ah[mt], Bh[nn * 2], Bh[nn * 2 + 1]);
            // group 2: Ah * Bl
#pragma unroll
            for (int mt = 0; mt < 4; mt++)
#pragma unroll
                for (int nn = 0; nn < 2; nn++)
                    mma16816(acc[mt][j * 2 + nn], Ah[mt], Bl[nn * 2], Bl[nn * 2 + 1]);
            // group 3: Al * Bh
#pragma unroll
            for (int mt = 0; mt < 4; mt++)
#pragma unroll
                for (int nn = 0; nn < 2; nn++)
                    mma16816(acc[mt][j * 2 + nn], Al[mt], Bh[nn * 2], Bh[nn * 2 + 1]);
        }
    }

    // ======== fused epilogue: +bias, LayerNorm(512), *gamma+beta, ReLU ========
    const int g = lane >> 2, t4 = lane & 3;
    float* ps = (float*)(smem + OFF_PS);      // [64 rows][8 warps]
    float* pq = (float*)(smem + OFF_PQ);
    float2* mz = (float2*)(smem + OFF_MZ);    // [64] {mu, rstd}

    float s[8], q[8];                          // row slots: mt*2 + h
#pragma unroll
    for (int r8 = 0; r8 < 8; r8++) { s[r8] = 0.f; q[r8] = 0.f; }

#pragma unroll
    for (int mt = 0; mt < 4; mt++) {
#pragma unroll
        for (int nt = 0; nt < 8; nt++) {
            const int col = wid * 64 + nt * 8 + t4 * 2;
            const float2 bv = *(const float2*)(bias + col);
            acc[mt][nt][0] += bv.x; acc[mt][nt][1] += bv.y;
            acc[mt][nt][2] += bv.x; acc[mt][nt][3] += bv.y;
            s[mt * 2 + 0] += acc[mt][nt][0] + acc[mt][nt][1];
            q[mt * 2 + 0] += acc[mt][nt][0] * acc[mt][nt][0]
                           + acc[mt][nt][1] * acc[mt][nt][1];
            s[mt * 2 + 1] += acc[mt][nt][2] + acc[mt][nt][3];
            q[mt * 2 + 1] += acc[mt][nt][2] * acc[mt][nt][2]
                           + acc[mt][nt][3] * acc[mt][nt][3];
        }
    }
#pragma unroll
    for (int r8 = 0; r8 < 8; r8++) {
        s[r8] += __shfl_xor_sync(0xffffffffu, s[r8], 1);
        q[r8] += __shfl_xor_sync(0xffffffffu, q[r8], 1);
        s[r8] += __shfl_xor_sync(0xffffffffu, s[r8], 2);
        q[r8] += __shfl_xor_sync(0xffffffffu, q[r8], 2);
    }
    if (t4 == 0) {
#pragma unroll
        for (int r8 = 0; r8 < 8; r8++) {
            const int row = (r8 >> 1) * 16 + (r8 & 1) * 8 + g;
            ps[row * 8 + wid] = s[r8];
            pq[row * 8 + wid] = q[r8];
        }
    }
    __syncthreads();
    if (tid < 64) {
        float ss = 0.f, qq = 0.f;
#pragma unroll
        for (int w = 0; w < 8; w++) { ss += ps[tid * 8 + w]; qq += pq[tid * 8 + w]; }
        const float mu  = ss * (1.0f / 512.0f);
        const float var = qq * (1.0f / 512.0f) - mu * mu;
        mz[tid] = make_float2(mu, rsqrtf(var + 1e-5f));
    }
    __syncthreads();

#pragma unroll
    for (int mt = 0; mt < 4; mt++) {
#pragma unroll
        for (int h = 0; h < 2; h++) {
            const int row = mt * 16 + h * 8 + g;
            const float2 m = mz[row];
#pragma unroll
            for (int nt = 0; nt < 8; nt++) {
                const int col = wid * 64 + nt * 8 + t4 * 2;
                const float2 gv = *(const float2*)(gamma + col);
                const float2 tv = *(const float2*)(beta + col);
                const float v0 = acc[mt][nt][h * 2 + 0];
                const float v1 = acc[mt][nt][h * 2 + 1];
                const float o0 = fmaxf((v0 - m.x) * m.y * gv.x + tv.x, 0.0f);
                const float o1 = fmaxf((v1 - m.x) * m.y * gv.y + tv.y, 0.0f);
                *(float2*)(out + (size_t)(m0 + row) * 512 + col) = make_float2(o0, o1);
            }
        }
    }
}

extern "C" void kernel_launch(void* const* d_in, const int* in_sizes, int n_in,
                              void* d_out, int out_size)
{
    // metadata order: embeddings, W_proj, b_proj, W_enc, b_enc, ln_gamma, ln_beta
    const float* emb   = (const float*)d_in[0];
    const float* W_enc = (const float*)d_in[3];
    const float* b_enc = (const float*)d_in[4];
    const float* gam   = (const float*)d_in[5];
    const float* bet   = (const float*)d_in[6];
    float* out = (float*)d_out;

    cudaFuncSetAttribute(gemm_ln_kernel,
                         cudaFuncAttributeMaxDynamicSharedMemorySize, SMEM_TOTAL);
    gemm_ln_kernel<<<16384 / MTILE, THREADS, SMEM_TOTAL>>>(emb, W_enc, b_enc,
                                                           gam, bet, out);
}